// round 10
// baseline (speedup 1.0000x reference)
#include <cuda_runtime.h>
#include <cstdint>
#include <math.h>

#define NB    128
#define H     128
#define NPG   8
#define BT    3
#define AA    243
#define PAIRS 192
#define TPB   512
#define ABST  132

typedef unsigned long long u64;
typedef unsigned int u32;

__device__ __forceinline__ u64 pack2(float lo, float hi) {
    u64 r; asm("mov.b64 %0, {%1, %2};" : "=l"(r) : "f"(lo), "f"(hi)); return r;
}
__device__ __forceinline__ void fma2(u64& d, u64 a, u64 b) {
    asm("fma.rn.f32x2 %0, %1, %2, %0;" : "+l"(d) : "l"(a), "l"(b));
}
__device__ __forceinline__ float2 unpack2(u64 v) {
    float2 f; asm("mov.b64 {%0, %1}, %2;" : "=f"(f.x), "=f"(f.y) : "l"(v)); return f;
}

__global__ __launch_bounds__(TPB, 1)
void fused_apm_kernel(const float* __restrict__ nf,      // (1024,128)
                      const float* __restrict__ mask,    // (128,243)
                      const float* __restrict__ Wfcv1,   // (128,64)
                      const float* __restrict__ bfcv1,   // (64)
                      const float* __restrict__ Wfcv2,   // (64,1)
                      const float* __restrict__ bfcv2,   // (1)
                      const float* __restrict__ Wa2,     // (256,128)
                      const float* __restrict__ ba2,     // (128)
                      const float* __restrict__ Wfin,    // (128,3)
                      const float* __restrict__ bfin,    // (3)
                      const int*   __restrict__ idxmask, // (128,243)
                      float* __restrict__ out)           // probs[128*243] ++ readout[128]
{
    const int b = blockIdx.x;
    const int t = threadIdx.x;

    __shared__ __align__(16) u64   ps[H][4];          // [c][node-pair]
    __shared__ __align__(16) float AB[2][NPG][ABST];  // final Ai/Bj
    __shared__ __align__(16) float sWfT[BT][H];
    __shared__ __align__(16) float sba[H];
    __shared__ __align__(16) float ssum[H];
    __shared__ float sc[PAIRS];
    __shared__ int   sidx[AA];
    __shared__ float smk[AA];
    __shared__ float red[16];

    // GEMM mapping: lane pairs split c-range
    const int ch  = t & 1;           // c-half within lane pair
    const int h   = (t >> 1) & 127;
    const int grp = t >> 8;          // 0 -> Ai, 1 -> Bj
    const float* Wp = Wa2 + grp * H * H + h;

    // ---- entry: every cold stream launched before the barrier ----
    if (t < AA) {
        sidx[t] = idxmask[b * AA + t];
        smk[t]  = mask[b * AA + t];
    }
    if (t >= 384) {                  // warm Wfcv1 into L2
        const char* base = (const char*)Wfcv1;
        int u = t - 384;
        asm volatile("prefetch.global.L2 [%0];" :: "l"(base + (u * 2 + 0) * 128));
        asm volatile("prefetch.global.L2 [%0];" :: "l"(base + (u * 2 + 1) * 128));
    }
    // prefetch ALL 64 of this thread's W values (per-thread c-range)
    float Wr[64];
    #pragma unroll
    for (int i = 0; i < 64; i++) Wr[i] = Wp[(ch * 64 + i) * H];

    // ---- stage node features: ps[c][pair] ----
    {
        const int c  = t & 127;
        const int nh = t >> 7;       // pair index 0..3
        float v0 = fmaxf(nf[(b * NPG + 2 * nh)     * H + c], 0.f);
        float v1 = fmaxf(nf[(b * NPG + 2 * nh + 1) * H + c], 0.f);
        ps[c][nh] = pack2(v0, v1);
    }
    if (t < H) {
        float a = 0.f;
        #pragma unroll
        for (int n = 0; n < NPG; n++) a += nf[(b * NPG + n) * H + t];
        ssum[t] = a;
        sba[t]  = ba2[t];
    } else if (t < H + H * BT) {
        int idx = t - H;
        int hh = idx & 127, k = idx >> 7;
        sWfT[k][hh] = Wfin[hh * BT + k];
    }
    __syncthreads();   // S1

    // ---- Ai/Bj GEMM: 8 nodes/thread over this lane's 64 c's; zero LDG inside ----
    {
        u64 acc0 = 0, acc1 = 0, acc2 = 0, acc3 = 0;   // pairs 0..3
        const ulonglong2* P = reinterpret_cast<const ulonglong2*>(&ps[ch * 64][0]);
        #pragma unroll 16
        for (int i = 0; i < 64; i++) {
            u64 wp = pack2(Wr[i], Wr[i]);
            ulonglong2 q01 = P[i * 2];
            ulonglong2 q23 = P[i * 2 + 1];
            fma2(acc0, q01.x, wp);
            fma2(acc1, q01.y, wp);
            fma2(acc2, q23.x, wp);
            fma2(acc3, q23.y, wp);
        }
        // lane-pair reduce (ch0 + ch1) via shfl; no barrier, no partial smem
        float2 f0 = unpack2(acc0), f1 = unpack2(acc1);
        float2 f2 = unpack2(acc2), f3 = unpack2(acc3);
        f0.x += __shfl_xor_sync(0xffffffffu, f0.x, 1);
        f0.y += __shfl_xor_sync(0xffffffffu, f0.y, 1);
        f1.x += __shfl_xor_sync(0xffffffffu, f1.x, 1);
        f1.y += __shfl_xor_sync(0xffffffffu, f1.y, 1);
        f2.x += __shfl_xor_sync(0xffffffffu, f2.x, 1);
        f2.y += __shfl_xor_sync(0xffffffffu, f2.y, 1);
        f3.x += __shfl_xor_sync(0xffffffffu, f3.x, 1);
        f3.y += __shfl_xor_sync(0xffffffffu, f3.y, 1);
        // even lanes store nodes 0-3, odd lanes nodes 4-7 (bank-skewed, conflict-free)
        float s0 = ch ? f2.x : f0.x;
        float s1 = ch ? f2.y : f0.y;
        float s2 = ch ? f3.x : f1.x;
        float s3 = ch ? f3.y : f1.y;
        const int nb0 = 4 * ch;
        AB[grp][nb0 + 0][h] = s0;
        AB[grp][nb0 + 1][h] = s1;
        AB[grp][nb0 + 2][h] = s2;
        AB[grp][nb0 + 3][h] = s3;
    }
    __syncthreads();   // S2

    // ---- pair scores (t<384, 2 threads/score) + readout MLP (t 384-511) ----
    if (t < 2 * PAIRS) {
        const int sid  = t >> 1;
        const int half = t & 1;
        const int k = sid >> 6;
        const int p = sid & 63;
        const int i = p >> 3, j = p & 7;
        const float4* A4 = reinterpret_cast<const float4*>(AB[0][i]);
        const float4* B4 = reinterpret_cast<const float4*>(AB[1][j]);
        const float4* W4 = reinterpret_cast<const float4*>(sWfT[k]);
        const float4* Z4 = reinterpret_cast<const float4*>(sba);
        float acc0 = 0.f, acc1 = 0.f;
        const int hb = half * 16;
        #pragma unroll
        for (int q = 0; q < 16; q += 2) {
            float4 a, bb, w, z;
            a = A4[hb + q]; bb = B4[hb + q]; w = W4[hb + q]; z = Z4[hb + q];
            acc0 += fmaxf(a.x + bb.x + z.x, 0.f) * w.x
                  + fmaxf(a.y + bb.y + z.y, 0.f) * w.y
                  + fmaxf(a.z + bb.z + z.z, 0.f) * w.z
                  + fmaxf(a.w + bb.w + z.w, 0.f) * w.w;
            a = A4[hb + q + 1]; bb = B4[hb + q + 1]; w = W4[hb + q + 1]; z = Z4[hb + q + 1];
            acc1 += fmaxf(a.x + bb.x + z.x, 0.f) * w.x
                  + fmaxf(a.y + bb.y + z.y, 0.f) * w.y
                  + fmaxf(a.z + bb.z + z.z, 0.f) * w.z
                  + fmaxf(a.w + bb.w + z.w, 0.f) * w.w;
        }
        float acc = acc0 + acc1;
        acc += __shfl_xor_sync(0xffffffffu, acc, 1);
        if (half == 0) sc[p * BT + k] = acc + bfin[k];
    } else {
        const int u    = t - 2 * PAIRS;
        const int j    = u >> 1;
        const int half = u & 1;
        const float4* S4 = reinterpret_cast<const float4*>(ssum);
        float acc0 = 0.f, acc1 = 0.f;
        const int cb = half * 16;
        #pragma unroll
        for (int q = 0; q < 16; q += 2) {
            float4 sv = S4[cb + q];
            int c = (cb + q) * 4;
            acc0 += sv.x * Wfcv1[(c + 0) * 64 + j] + sv.y * Wfcv1[(c + 1) * 64 + j]
                  + sv.z * Wfcv1[(c + 2) * 64 + j] + sv.w * Wfcv1[(c + 3) * 64 + j];
            sv = S4[cb + q + 1];
            c = (cb + q + 1) * 4;
            acc1 += sv.x * Wfcv1[(c + 0) * 64 + j] + sv.y * Wfcv1[(c + 1) * 64 + j]
                  + sv.z * Wfcv1[(c + 2) * 64 + j] + sv.w * Wfcv1[(c + 3) * 64 + j];
        }
        float tot = acc0 + acc1;
        tot += __shfl_xor_sync(0xffffffffu, tot, 1);
        float hid = (half == 0) ? fmaxf(tot + bfcv1[j], 0.f) * Wfcv2[j] : 0.f;
        #pragma unroll
        for (int off = 16; off > 0; off >>= 1)
            hid += __shfl_down_sync(0xffffffffu, hid, off);
        if ((t & 31) == 0) red[t >> 5] = hid;     // red[12..15]
    }
    __syncthreads();   // S3

    // ---- warp 0 finishes softmax + readout store ----
    if (t < 32) {
        if (t == 0)
            out[NB * AA + b] = ((red[12] + red[13]) + (red[14] + red[15])) + bfcv2[0];

        float fv[8];
        #pragma unroll
        for (int q = 0; q < 8; q++) {
            int e = t + 32 * q;
            if (e < AA) {
                int im = sidx[e];
                fv[q] = ((im < PAIRS) ? sc[im] : 0.f) + smk[e];
            } else fv[q] = -INFINITY;
        }
        float m = fv[0];
        #pragma unroll
        for (int q = 1; q < 8; q++) m = fmaxf(m, fv[q]);
        #pragma unroll
        for (int off = 16; off > 0; off >>= 1)
            m = fmaxf(m, __shfl_xor_sync(0xffffffffu, m, off));
        float sr = 0.f;
        #pragma unroll
        for (int q = 0; q < 8; q++) {
            fv[q] = (fv[q] == -INFINITY) ? 0.f : __expf(fv[q] - m);
            sr += fv[q];
        }
        #pragma unroll
        for (int off = 16; off > 0; off >>= 1)
            sr += __shfl_xor_sync(0xffffffffu, sr, off);
        float inv = 1.f / sr;
        #pragma unroll
        for (int q = 0; q < 8; q++) {
            int e = t + 32 * q;
            if (e < AA) out[b * AA + e] = fv[q] * inv;
        }
    }
}

extern "C" void kernel_launch(void* const* d_in, const int* in_sizes, int n_in,
                              void* d_out, int out_size) {
    const float* nf     = (const float*)d_in[0];
    const float* mask   = (const float*)d_in[2];
    const float* Wfcv1  = (const float*)d_in[3];
    const float* bfcv1  = (const float*)d_in[4];
    const float* Wfcv2  = (const float*)d_in[5];
    const float* bfcv2  = (const float*)d_in[6];
    const float* Wa2    = (const float*)d_in[7];
    const float* ba2    = (const float*)d_in[8];
    const float* Wfin   = (const float*)d_in[9];
    const float* bfin   = (const float*)d_in[10];
    const int*   idxm   = (const int*)d_in[11];
    float* out = (float*)d_out;

    fused_apm_kernel<<<NB, TPB>>>(nf, mask, Wfcv1, bfcv1, Wfcv2, bfcv2,
                                  Wa2, ba2, Wfin, bfin, idxm, out);
}

// round 11
// speedup vs baseline: 1.4130x; 1.4130x over previous
#include <cuda_runtime.h>
#include <cstdint>
#include <math.h>

#define NB    128
#define H     128
#define NPG   8
#define BT    3
#define AA    243
#define PAIRS 192
#define ABST  132

typedef unsigned long long u64;

__device__ __forceinline__ u64 pack2(float lo, float hi) {
    u64 r; asm("mov.b64 %0, {%1, %2};" : "=l"(r) : "f"(lo), "f"(hi)); return r;
}
__device__ __forceinline__ void fma2(u64& d, u64 a, u64 b) {
    asm("fma.rn.f32x2 %0, %1, %2, %0;" : "+l"(d) : "l"(a), "l"(b));
}
__device__ __forceinline__ float2 unpack2(u64 v) {
    float2 f; asm("mov.b64 {%0, %1}, %2;" : "=f"(f.x), "=f"(f.y) : "l"(v)); return f;
}

// AB scratch: [graph][grp][node][h]  (1 MB, device-global — allocation-free rule OK)
__device__ float ABg[NB * 2 * NPG * H];

// ---------------- K1: Ai/Bj GEMM -> ABg ----------------
__global__ __launch_bounds__(256, 2)
void apm_gemm_kernel(const float* __restrict__ nf,
                     const float* __restrict__ Wa2)
{
    const int b   = blockIdx.x >> 1;
    const int grp = blockIdx.x & 1;
    const int t   = threadIdx.x;

    __shared__ __align__(16) u64 ps[H][4];    // [c][node-pair]

    const int h = t & 127;
    const int X = t >> 7;                     // node quad 4X..4X+3
    const float* Wp = Wa2 + grp * H * H + h;

    float Wr[32];
    #pragma unroll
    for (int i = 0; i < 32; i++) Wr[i] = Wp[i * H];   // batch 0 pre-barrier

    // stage relu'd node features, node-pair packed (2 entries/thread)
    #pragma unroll
    for (int idx = t; idx < 4 * H; idx += 256) {
        int nh = idx >> 7, c = idx & 127;
        float v0 = fmaxf(nf[(b * NPG + 2 * nh)     * H + c], 0.f);
        float v1 = fmaxf(nf[(b * NPG + 2 * nh + 1) * H + c], 0.f);
        ps[c][nh] = pack2(v0, v1);
    }
    __syncthreads();

    u64 acc0 = 0, acc1 = 0;                   // node pairs 2X, 2X+1
    #pragma unroll
    for (int batch = 0; batch < 4; batch++) {
        if (batch) {
            #pragma unroll
            for (int i = 0; i < 32; i++) Wr[i] = Wp[(batch * 32 + i) * H];
        }
        #pragma unroll
        for (int cc = 0; cc < 32; cc++) {
            const int c = batch * 32 + cc;
            u64 wp = pack2(Wr[cc], Wr[cc]);
            ulonglong2 q = *reinterpret_cast<const ulonglong2*>(&ps[c][X * 2]);
            fma2(acc0, q.x, wp);
            fma2(acc1, q.y, wp);
        }
    }
    float2 f0 = unpack2(acc0);
    float2 f1 = unpack2(acc1);
    float* dst = ABg + ((b * 2 + grp) * NPG) * H;
    dst[(4 * X + 0) * H + h] = f0.x;
    dst[(4 * X + 1) * H + h] = f0.y;
    dst[(4 * X + 2) * H + h] = f1.x;
    dst[(4 * X + 3) * H + h] = f1.y;
}

// ---------------- K2: scores + softmax + readout ----------------
__global__ __launch_bounds__(256, 2)
void apm_tail_kernel(const float* __restrict__ nf,
                     const float* __restrict__ mask,
                     const float* __restrict__ Wfcv1,
                     const float* __restrict__ bfcv1,
                     const float* __restrict__ Wfcv2,
                     const float* __restrict__ bfcv2,
                     const float* __restrict__ ba2,
                     const float* __restrict__ Wfin,
                     const float* __restrict__ bfin,
                     const int*   __restrict__ idxmask,
                     float* __restrict__ out)
{
    const int b = blockIdx.x;
    const int t = threadIdx.x;

    __shared__ __align__(16) float ABs[2][NPG][ABST];
    __shared__ __align__(16) float sWfT[BT][H];
    __shared__ __align__(16) float sba[H];
    __shared__ __align__(16) float ssum[H];
    __shared__ float sc[PAIRS];
    __shared__ int   sidx[AA];
    __shared__ float smk[AA];
    __shared__ float red[2];

    // stage AB (8 KB, L2-hot) into padded smem: 2 float4 per thread
    {
        const float4* src = reinterpret_cast<const float4*>(ABg + b * 2 * NPG * H);
        #pragma unroll
        for (int v = 0; v < 2; v++) {
            int g = t + v * 256;              // float4 index 0..511
            float4 val = src[g];
            int row = g >> 5;                 // 0..15 = grp*8+n
            int hh  = (g & 31) * 4;
            *reinterpret_cast<float4*>(&ABs[row >> 3][row & 7][hh]) = val;
        }
    }
    if (t < H) {                              // ssum + sba
        float a = 0.f;
        #pragma unroll
        for (int n = 0; n < NPG; n++) a += nf[(b * NPG + n) * H + t];
        ssum[t] = a;
        sba[t]  = ba2[t];
    }
    #pragma unroll
    for (int idx = t; idx < H * BT; idx += 256) {
        int hh = idx & 127, k = idx >> 7;
        sWfT[k][hh] = Wfin[hh * BT + k];
    }
    #pragma unroll
    for (int idx = t; idx < AA; idx += 256) {
        sidx[idx] = idxmask[b * AA + idx];
        smk[idx]  = mask[b * AA + idx];
    }
    __syncthreads();   // S1

    // scores (t<192, one thread/score) + readout (t 192-255)
    if (t < PAIRS) {
        const int k = t >> 6;
        const int p = t & 63;
        const int i = p >> 3, j = p & 7;
        const float4* A4 = reinterpret_cast<const float4*>(ABs[0][i]);
        const float4* B4 = reinterpret_cast<const float4*>(ABs[1][j]);
        const float4* W4 = reinterpret_cast<const float4*>(sWfT[k]);
        const float4* Z4 = reinterpret_cast<const float4*>(sba);
        float acc0 = 0.f, acc1 = 0.f;
        #pragma unroll
        for (int q = 0; q < 32; q += 2) {
            float4 a, bb, w, z;
            a = A4[q]; bb = B4[q]; w = W4[q]; z = Z4[q];
            acc0 += fmaxf(a.x + bb.x + z.x, 0.f) * w.x
                  + fmaxf(a.y + bb.y + z.y, 0.f) * w.y
                  + fmaxf(a.z + bb.z + z.z, 0.f) * w.z
                  + fmaxf(a.w + bb.w + z.w, 0.f) * w.w;
            a = A4[q + 1]; bb = B4[q + 1]; w = W4[q + 1]; z = Z4[q + 1];
            acc1 += fmaxf(a.x + bb.x + z.x, 0.f) * w.x
                  + fmaxf(a.y + bb.y + z.y, 0.f) * w.y
                  + fmaxf(a.z + bb.z + z.z, 0.f) * w.z
                  + fmaxf(a.w + bb.w + z.w, 0.f) * w.w;
        }
        sc[p * BT + k] = acc0 + acc1 + bfin[k];
    } else {
        const int j = t - PAIRS;              // 0..63
        const float4* S4 = reinterpret_cast<const float4*>(ssum);
        float acc0 = 0.f, acc1 = 0.f;
        #pragma unroll
        for (int q = 0; q < 32; q += 2) {
            float4 sv = S4[q];
            int c = q * 4;
            acc0 += sv.x * Wfcv1[(c + 0) * 64 + j] + sv.y * Wfcv1[(c + 1) * 64 + j]
                  + sv.z * Wfcv1[(c + 2) * 64 + j] + sv.w * Wfcv1[(c + 3) * 64 + j];
            sv = S4[q + 1];
            c = (q + 1) * 4;
            acc1 += sv.x * Wfcv1[(c + 0) * 64 + j] + sv.y * Wfcv1[(c + 1) * 64 + j]
                  + sv.z * Wfcv1[(c + 2) * 64 + j] + sv.w * Wfcv1[(c + 3) * 64 + j];
        }
        float hid = fmaxf(acc0 + acc1 + bfcv1[j], 0.f) * Wfcv2[j];
        #pragma unroll
        for (int off = 16; off > 0; off >>= 1)
            hid += __shfl_down_sync(0xffffffffu, hid, off);
        if ((t & 31) == 0) red[(t >> 5) - 6] = hid;
    }
    __syncthreads();   // S2

    // warp 0: readout store + gather + softmax; other warps retire
    if (t < 32) {
        if (t == 0) out[NB * AA + b] = red[0] + red[1] + bfcv2[0];

        float fv[8];
        #pragma unroll
        for (int q = 0; q < 8; q++) {
            int e = t + 32 * q;
            if (e < AA) {
                int im = sidx[e];
                fv[q] = ((im < PAIRS) ? sc[im] : 0.f) + smk[e];
            } else fv[q] = -INFINITY;
        }
        float m = fv[0];
        #pragma unroll
        for (int q = 1; q < 8; q++) m = fmaxf(m, fv[q]);
        #pragma unroll
        for (int off = 16; off > 0; off >>= 1)
            m = fmaxf(m, __shfl_xor_sync(0xffffffffu, m, off));
        float sr = 0.f;
        #pragma unroll
        for (int q = 0; q < 8; q++) {
            fv[q] = (fv[q] == -INFINITY) ? 0.f : __expf(fv[q] - m);
            sr += fv[q];
        }
        #pragma unroll
        for (int off = 16; off > 0; off >>= 1)
            sr += __shfl_xor_sync(0xffffffffu, sr, off);
        float inv = 1.f / sr;
        #pragma unroll
        for (int q = 0; q < 8; q++) {
            int e = t + 32 * q;
            if (e < AA) out[b * AA + e] = fv[q] * inv;
        }
    }
}

extern "C" void kernel_launch(void* const* d_in, const int* in_sizes, int n_in,
                              void* d_out, int out_size) {
    const float* nf     = (const float*)d_in[0];
    const float* mask   = (const float*)d_in[2];
    const float* Wfcv1  = (const float*)d_in[3];
    const float* bfcv1  = (const float*)d_in[4];
    const float* Wfcv2  = (const float*)d_in[5];
    const float* bfcv2  = (const float*)d_in[6];
    const float* Wa2    = (const float*)d_in[7];
    const float* ba2    = (const float*)d_in[8];
    const float* Wfin   = (const float*)d_in[9];
    const float* bfin   = (const float*)d_in[10];
    const int*   idxm   = (const int*)d_in[11];
    float* out = (float*)d_out;

    apm_gemm_kernel<<<2 * NB, 256>>>(nf, Wa2);
    apm_tail_kernel<<<NB, 256>>>(nf, mask, Wfcv1, bfcv1, Wfcv2, bfcv2,
                                 ba2, Wfin, bfin, idxm, out);
}